// round 4
// baseline (speedup 1.0000x reference)
#include <cuda_runtime.h>
#include <cstdint>

#define NTPL 10
#define NACC 11                                   // 10 cross + 1 x·x
#define PIX 784
#define TILE_IMGS 32
#define CHUNKS 196                                // float4 chunks per image
#define NW 24                                     // warps per block
#define THREADS (NW * 32)                         // 768
#define IMG_BYTES 3136                            // PIX*4, 16B aligned
#define IMG_STRIDE 3152                           // +16B pad: 788 words == 20 mod 32 -> conflict-free
#define STAGE_BYTES (TILE_IMGS * IMG_STRIDE)      // 100864
#define MBAR_OFF (2 * STAGE_BYTES)                // 201728 (two 8B mbarriers)
#define TSQ_OFF (MBAR_OFF + 64)                   // t_sq, 10 doubles
#define SMEM_TOTAL (TSQ_OFF + 128)                // 201920 <= 232448 opt-in max

__constant__ ulonglong2 ctpl[NTPL * CHUNKS];      // templates: [k][chunk] 16B granules

#define FMA2(acc, a, b) \
    asm("fma.rn.f32x2 %0, %1, %2, %0;" : "+l"(acc) : "l"(a), "l"(b))

__device__ __forceinline__ void mbar_wait(uint32_t addr, uint32_t phase) {
    uint32_t done = 0;
    while (!done) {
        asm volatile(
            "{\n\t.reg .pred p;\n\t"
            "mbarrier.try_wait.parity.acquire.cta.shared::cta.b64 p, [%1], %2, 0x989680;\n\t"
            "selp.b32 %0, 1, 0, p;\n\t}"
            : "=r"(done) : "r"(addr), "r"(phase) : "memory");
    }
}

// One thread: fetch a 32-image tile via 32 bulk copies into padded-stride smem.
__device__ __forceinline__ void issue_tile_bulk(int tile, int ntiles, uint32_t sbase,
                                                uint32_t mbar, const char* __restrict__ xg) {
    if (tile < ntiles) {
        asm volatile("mbarrier.arrive.expect_tx.shared.b64 _, [%0], %1;"
                     :: "r"(mbar), "r"((uint32_t)(TILE_IMGS * IMG_BYTES)) : "memory");
        const char* src = xg + (size_t)tile * (TILE_IMGS * IMG_BYTES);
        #pragma unroll
        for (int i = 0; i < TILE_IMGS; i++) {
            asm volatile(
                "cp.async.bulk.shared::cta.global.mbarrier::complete_tx::bytes "
                "[%0], [%1], %2, [%3];"
                :: "r"(sbase + (uint32_t)(i * IMG_STRIDE)),
                   "l"(src + (size_t)i * IMG_BYTES),
                   "r"((uint32_t)IMG_BYTES), "r"(mbar) : "memory");
        }
    }
}

__global__ void __launch_bounds__(THREADS, 1)
mse_argmin_kernel(const float* __restrict__ xg, const float* __restrict__ tg,
                  float* __restrict__ out, int ntiles) {
    extern __shared__ float sm[];
    const uint32_t smb = (uint32_t)__cvta_generic_to_shared(sm);
    const int tid = threadIdx.x;
    const int w = tid >> 5;
    const int lane = tid & 31;
    const int G = gridDim.x;
    const int t0 = blockIdx.x;
    const char* xgc = (const char*)xg;

    // mbarrier init (count=1), visible to the async proxy before first bulk.
    if (tid == 0) {
        asm volatile("mbarrier.init.shared.b64 [%0], 1;" :: "r"(smb + MBAR_OFF) : "memory");
        asm volatile("mbarrier.init.shared.b64 [%0], 1;" :: "r"(smb + MBAR_OFF + 16) : "memory");
        asm volatile("fence.proxy.async;" ::: "memory");
    }
    __syncthreads();

    // Prologue: get DRAM moving.
    if (tid == 0) {
        issue_tile_bulk(t0, ntiles, smb + 0u, smb + MBAR_OFF, xgc);
        issue_tile_bulk(t0 + G, ntiles, smb + STAGE_BYTES, smb + MBAR_OFF + 16, xgc);
    }

    // Exact (fp64) squared template norms straight from gmem: one warp per
    // template, lane-strided partials + fp64 butterfly (same as R3: rel_err 0).
    double* tsq_d = (double*)(sm + (TSQ_OFF >> 2));
    if (w < NTPL) {
        const float* tp = tg + w * PIX;
        double a = 0.0;
        for (int p = lane; p < PIX; p += 32) a = fma((double)tp[p], (double)tp[p], a);
        #pragma unroll
        for (int s = 16; s > 0; s >>= 1) a += __shfl_xor_sync(0xffffffffu, a, s);
        if (lane == 0) tsq_d[w] = a;
    }
    __syncthreads();

    uint32_t ph0 = 0, ph1 = 0;   // per-stage mbarrier phase parity
    int stage = 0;
    for (int t = t0; t < ntiles; t += G, stage ^= 1) {
        const uint32_t soff = stage ? (uint32_t)STAGE_BYTES : 0u;
        const uint32_t sbase = smb + soff;
        const uint32_t mbar = smb + MBAR_OFF + (stage ? 16u : 0u);

        if (stage == 0) { mbar_wait(mbar, ph0); ph0 ^= 1; }
        else            { mbar_wait(mbar, ph1); ph1 ^= 1; }
        __syncthreads();

        // ---- main loop: lane = image, warp covers chunks c = w, w+NW, ... ----
        // x from padded smem (conflict-free LDS.128); templates from __constant__
        // with warp-uniform index -> LDCU, zero crossbar traffic.
        uint64_t acc[NACC];
        #pragma unroll
        for (int k = 0; k < NACC; k++) acc[k] = 0ull;

        uint32_t xaddr = sbase + (uint32_t)lane * IMG_STRIDE + (uint32_t)w * 16u;
        const int niter = (w < (CHUNKS % NW)) ? (CHUNKS / NW + 1) : (CHUNKS / NW);
        int c = w;
        #pragma unroll 1
        for (int i = 0; i < niter; i++) {
            uint64_t x01, x23;
            asm("ld.shared.v2.u64 {%0, %1}, [%2];"
                : "=l"(x01), "=l"(x23) : "r"(xaddr));
            const ulonglong2* tp = ctpl + c;
            #pragma unroll
            for (int k = 0; k < NTPL; k++) {
                const ulonglong2 tv = tp[k * CHUNKS];
                FMA2(acc[k], x01, tv.x);
                FMA2(acc[k], x23, tv.y);
            }
            FMA2(acc[NTPL], x01, x01);       // x·x for the reference formula
            FMA2(acc[NTPL], x23, x23);
            xaddr += (uint32_t)NW * 16u;
            c += NW;
        }
        __syncthreads();   // all warps done reading stage -> safe to reuse as scratch

        // ---- per-lane fold + per-warp fp32 partials into stage scratch ----
        float* red = sm + (soff >> 2);          // [k][warp][lane] : 11*24*32 floats
        #pragma unroll
        for (int k = 0; k < NACC; k++) {
            uint32_t lo, hi;
            asm("mov.b64 {%0, %1}, %2;" : "=r"(lo), "=r"(hi) : "l"(acc[k]));
            red[k * (NW * 32) + w * 32 + lane] = __uint_as_float(lo) + __uint_as_float(hi);
        }
        __syncthreads();

        // ---- cross-warp reduction in fp64 (pairwise tree, depth ~5) ----
        double* dsum = (double*)(red + NACC * NW * 32);   // [k][img] : 11*32 doubles
        if (tid < NACC * TILE_IMGS) {
            const int img = tid & 31, k = tid >> 5;
            const float* rp = red + k * (NW * 32) + img;
            double v[NW];
            #pragma unroll
            for (int ww = 0; ww < NW; ww++) v[ww] = (double)rp[ww * 32];
            #pragma unroll
            for (int n = NW; n > 1; n = (n + 1) >> 1) {
                const int h = n >> 1;
                #pragma unroll
                for (int j = 0; j < h; j++) v[j] += v[j + n - h];
            }
            dsum[k * 32 + img] = v[0];
        }
        __syncthreads();

        // ---- distances in fp64, rounded to fp32 exactly like the reference,
        //      then argmin (strict <, first index wins ties == jnp.argmin) ----
        if (tid < TILE_IMGS) {
            const double xx = dsum[NTPL * 32 + tid];
            float best = 0.f;
            int bi = 0;
            #pragma unroll
            for (int k = 0; k < NTPL; k++) {
                const double cross = dsum[k * 32 + tid];
                const float v = (float)((xx - 2.0 * cross + tsq_d[k]) / (double)PIX);
                if (k == 0 || v < best) { best = v; bi = k; }
            }
            out[(size_t)t * TILE_IMGS + tid] = (float)bi;
        }
        __syncthreads();   // scratch reads done before bulk overwrites stage

        // ---- refill this stage with tile t+2G ----
        if (tid == 0) issue_tile_bulk(t + 2 * G, ntiles, sbase, mbar, xgc);
    }
}

extern "C" void kernel_launch(void* const* d_in, const int* in_sizes, int n_in,
                              void* d_out, int out_size) {
    // Robust to input ordering: x is the big one.
    const float* a = (const float*)d_in[0];
    const float* b = (const float*)d_in[1];
    const float* xg;
    const float* tg;
    long nx;
    if (in_sizes[0] >= in_sizes[1]) { xg = a; tg = b; nx = in_sizes[0]; }
    else                            { xg = b; tg = a; nx = in_sizes[1]; }

    const int B = (int)(nx / PIX);
    const int ntiles = B / TILE_IMGS;   // 262144/32 = 8192, exact

    // Templates -> constant bank (async D2D, graph-capturable).
    cudaMemcpyToSymbolAsync(ctpl, tg, NTPL * PIX * sizeof(float), 0,
                            cudaMemcpyDeviceToDevice, 0);

    int dev = 0;
    cudaGetDevice(&dev);
    int nsm = 148;
    cudaDeviceGetAttribute(&nsm, cudaDevAttrMultiProcessorCount, dev);
    int grid = nsm < ntiles ? nsm : ntiles;

    cudaFuncSetAttribute(mse_argmin_kernel,
                         cudaFuncAttributeMaxDynamicSharedMemorySize, SMEM_TOTAL);

    mse_argmin_kernel<<<grid, THREADS, SMEM_TOTAL>>>(xg, tg, (float*)d_out, ntiles);
}

// round 5
// speedup vs baseline: 3.8809x; 3.8809x over previous
#include <cuda_runtime.h>
#include <cstdint>

#define NTPL 10
#define NACC 11                                   // 10 cross + 1 x·x
#define PIX 784
#define TILE_IMGS 32
#define CHUNKS 196                                // float4 chunks per image
#define NW 24                                     // warps per block
#define THREADS (NW * 32)                         // 768
#define IMG_BYTES 3136                            // PIX*4
#define STAGE_BYTES (TILE_IMGS * IMG_BYTES)       // 100352 (contiguous, = gmem tile)
#define TM_OFF (2 * STAGE_BYTES)                  // 200704 templates [k][chunk] 16B
#define SPARE (TM_OFF + NTPL * PIX * 4)           // 232064
#define MBAR0 (SPARE + 0)
#define MBAR1 (SPARE + 16)
#define TSQ_OFF (SPARE + 32)                      // 10 doubles (80 B)
#define XXD_OFF (SPARE + 112)                     // 32 doubles (256 B)
#define SMEM_TOTAL (SPARE + 384)                  // 232448 == opt-in max

#define FMA2(acc, a, b) \
    asm("fma.rn.f32x2 %0, %1, %2, %0;" : "+l"(acc) : "l"(a), "l"(b))

__device__ __forceinline__ void mbar_wait(uint32_t addr, uint32_t phase) {
    uint32_t done = 0;
    while (!done) {
        asm volatile(
            "{\n\t.reg .pred p;\n\t"
            "mbarrier.try_wait.parity.acquire.cta.shared::cta.b64 p, [%1], %2, 0x989680;\n\t"
            "selp.b32 %0, 1, 0, p;\n\t}"
            : "=r"(done) : "r"(addr), "r"(phase) : "memory");
    }
}

// One thread: fetch a whole contiguous 32-image tile with a single bulk copy.
__device__ __forceinline__ void issue_tile_bulk(int tile, int ntiles, uint32_t sbase,
                                                uint32_t mbar, const char* __restrict__ xg) {
    if (tile < ntiles) {
        asm volatile("mbarrier.arrive.expect_tx.shared.b64 _, [%0], %1;"
                     :: "r"(mbar), "r"((uint32_t)STAGE_BYTES) : "memory");
        asm volatile(
            "cp.async.bulk.shared::cta.global.mbarrier::complete_tx::bytes "
            "[%0], [%1], %2, [%3];"
            :: "r"(sbase), "l"(xg + (size_t)tile * STAGE_BYTES),
               "r"((uint32_t)STAGE_BYTES), "r"(mbar) : "memory");
    }
}

__global__ void __launch_bounds__(THREADS, 1)
mse_argmin_kernel(const float* __restrict__ xg, const float* __restrict__ tg,
                  float* __restrict__ out, int ntiles) {
    extern __shared__ float sm[];
    const uint32_t smb = (uint32_t)__cvta_generic_to_shared(sm);
    const int tid = threadIdx.x;
    const int w = tid >> 5;
    const int lane = tid & 31;
    const int G = gridDim.x;
    const int t0 = blockIdx.x;
    const char* xgc = (const char*)xg;
    const double INV784 = 1.0 / 784.0;

    if (tid == 0) {
        asm volatile("mbarrier.init.shared.b64 [%0], 1;" :: "r"(smb + MBAR0) : "memory");
        asm volatile("mbarrier.init.shared.b64 [%0], 1;" :: "r"(smb + MBAR1) : "memory");
        asm volatile("fence.proxy.async;" ::: "memory");
    }
    __syncthreads();

    // Prologue: get DRAM moving before anything else.
    if (tid == 0) {
        issue_tile_bulk(t0, ntiles, smb + 0u, smb + MBAR0, xgc);
        issue_tile_bulk(t0 + G, ntiles, smb + STAGE_BYTES, smb + MBAR1, xgc);
    }

    // Templates -> smem (vectorized, once per block).
    {
        const float4* tg4 = (const float4*)tg;
        float4* tm4 = (float4*)(sm + (TM_OFF >> 2));
        for (int i = tid; i < NTPL * CHUNKS; i += THREADS) tm4[i] = tg4[i];
    }
    // Exact (fp64) squared template norms: one warp per template (amortized).
    double* tsq_d = (double*)((char*)sm + TSQ_OFF);
    if (w < NTPL) {
        const float* tp = tg + w * PIX;
        double a = 0.0;
        for (int p = lane; p < PIX; p += 32) a = fma((double)tp[p], (double)tp[p], a);
        #pragma unroll
        for (int s = 16; s > 0; s >>= 1) a += __shfl_xor_sync(0xffffffffu, a, s);
        if (lane == 0) tsq_d[w] = a;
    }
    __syncthreads();

    double* xxd = (double*)((char*)sm + XXD_OFF);
    uint32_t ph0 = 0, ph1 = 0;
    int stage = 0;
    for (int t = t0; t < ntiles; t += G, stage ^= 1) {
        const uint32_t soff = stage ? (uint32_t)STAGE_BYTES : 0u;
        const uint32_t sbase = smb + soff;
        const uint32_t mbar = smb + (stage ? MBAR1 : MBAR0);

        if (stage == 0) { mbar_wait(mbar, ph0); ph0 ^= 1; }
        else            { mbar_wait(mbar, ph1); ph1 ^= 1; }
        __syncthreads();

        // ---- main loop: lane = image (contiguous layout), warp strides chunks ----
        uint64_t acc[NACC];
        #pragma unroll
        for (int k = 0; k < NACC; k++) acc[k] = 0ull;

        uint32_t xaddr = sbase + (uint32_t)lane * IMG_BYTES + (uint32_t)w * 16u;
        uint32_t taddr = smb + TM_OFF + (uint32_t)w * 16u;
        const int niter = (w < (CHUNKS % NW)) ? (CHUNKS / NW + 1) : (CHUNKS / NW);
        #pragma unroll 2
        for (int i = 0; i < niter; i++) {
            uint64_t x01, x23;
            asm("ld.shared.v2.u64 {%0, %1}, [%2];"
                : "=l"(x01), "=l"(x23) : "r"(xaddr));
            #pragma unroll
            for (int k = 0; k < NTPL; k++) {           // templates [k][chunk]
                uint64_t a01, a23;
                asm("ld.shared.v2.u64 {%0, %1}, [%2];"
                    : "=l"(a01), "=l"(a23) : "r"(taddr + (uint32_t)(k * CHUNKS * 16)));
                FMA2(acc[k], x01, a01);
                FMA2(acc[k], x23, a23);
            }
            FMA2(acc[NTPL], x01, x01);                 // x·x
            FMA2(acc[NTPL], x23, x23);
            xaddr += (uint32_t)NW * 16u;
            taddr += (uint32_t)NW * 16u;
        }
        __syncthreads();   // stage data consumed -> reuse as scratch

        // ---- A: per-lane hi+lo fp32 fold (identical to R3) -> red scratch ----
        float* red = sm + (soff >> 2);                 // [k][warp][lane]
        #pragma unroll
        for (int k = 0; k < NACC; k++) {
            uint32_t lo, hi;
            asm("mov.b64 {%0, %1}, %2;" : "=r"(lo), "=r"(hi) : "l"(acc[k]));
            red[k * THREADS + w * 32 + lane] = __uint_as_float(lo) + __uint_as_float(hi);
        }
        __syncthreads();

        // ---- B: exact 24-way fold via fp32 TwoSum cascade (error-free) ----
        float fs = 0.f, fe = 0.f;
        const int img = tid & 31, k = tid >> 5;
        if (tid < NACC * TILE_IMGS) {
            const float* rp = red + k * THREADS + img;
            #pragma unroll
            for (int ww = 0; ww < NW; ww++) {
                const float v = rp[ww * 32];
                const float tt = fs + v;
                const float z = tt - fs;
                fe += (fs - (tt - z)) + (v - z);       // exact residual
                fs = tt;
            }
            if (k == NTPL) xxd[img] = (double)fs + (double)fe;   // x·x, fp64
        }
        __syncthreads();

        // ---- C: distances in fp64 (equiv to R3 within 1e-15), fp32 round ----
        if (tid < NTPL * TILE_IMGS) {
            const double c = (double)fs + (double)fe;
            const double v = (fma(-2.0, c, xxd[img]) + tsq_d[k]) * INV784;
            red[k * 32 + img] = (float)v;              // d[k][img] in dead scratch
        }
        __syncthreads();

        // ---- D: argmin (strict <, first index wins == jnp.argmin), refill ----
        if (tid < TILE_IMGS) {
            float best = red[tid];
            int bi = 0;
            #pragma unroll
            for (int kk = 1; kk < NTPL; kk++) {
                const float v = red[kk * 32 + tid];
                if (v < best) { best = v; bi = kk; }
            }
            out[(size_t)t * TILE_IMGS + tid] = (float)bi;
            if (tid == 0) issue_tile_bulk(t + 2 * G, ntiles, sbase, mbar, xgc);
        }
    }
}

extern "C" void kernel_launch(void* const* d_in, const int* in_sizes, int n_in,
                              void* d_out, int out_size) {
    // Robust to input ordering: x is the big one.
    const float* a = (const float*)d_in[0];
    const float* b = (const float*)d_in[1];
    const float* xg;
    const float* tg;
    long nx;
    if (in_sizes[0] >= in_sizes[1]) { xg = a; tg = b; nx = in_sizes[0]; }
    else                            { xg = b; tg = a; nx = in_sizes[1]; }

    const int B = (int)(nx / PIX);
    const int ntiles = B / TILE_IMGS;   // 262144/32 = 8192, exact

    int dev = 0;
    cudaGetDevice(&dev);
    int nsm = 148;
    cudaDeviceGetAttribute(&nsm, cudaDevAttrMultiProcessorCount, dev);
    int grid = nsm < ntiles ? nsm : ntiles;

    cudaFuncSetAttribute(mse_argmin_kernel,
                         cudaFuncAttributeMaxDynamicSharedMemorySize, SMEM_TOTAL);

    mse_argmin_kernel<<<grid, THREADS, SMEM_TOTAL>>>(xg, tg, (float*)d_out, ntiles);
}